// round 4
// baseline (speedup 1.0000x reference)
#include <cuda_runtime.h>

#define N_NODES 50000
#define N_EDGES 1600000
#define DIM 128
#define NHEAD 8

// ---- scratch (static device globals; no runtime allocation) ----
__device__ float g_x[N_NODES * DIM];        // projected features [N,128]
__device__ float g_al[N_NODES * NHEAD];     // left logits  [N,8]
__device__ float g_ar[N_NODES * NHEAD];     // right logits [N,8]
__device__ int   g_count[N_NODES];          // per-dst edge counts
__device__ int   g_rowptr[N_NODES + 1];     // CSR row pointers
__device__ int   g_cursor[N_NODES];         // scatter cursors
__device__ int2  g_edge[N_EDGES];           // dst-sorted (src, weight_bits)

typedef unsigned long long ull;

__device__ __forceinline__ ull fma2(ull a, ull b, ull c) {
    ull d;
    asm("fma.rn.f32x2 %0, %1, %2, %3;" : "=l"(d) : "l"(a), "l"(b), "l"(c));
    return d;
}

// ---------------- zero counters ----------------
__global__ void k_zero() {
    int i = blockIdx.x * blockDim.x + threadIdx.x;
    if (i < N_NODES) g_count[i] = 0;
}

// ---------------- fused dual GEMM: x = F@Wlin, res = F@Wres ----------------
// Packed f32x2: accumulator holds (sum over even k, sum over odd k).
// Block: 256 thr = 8 warps, 32 nodes/block (4 nodes/warp). Lane owns cols
// {lane, lane+32, lane+64, lane+96}. K tiled 2x64. W tile stored transposed
// (sW_T[col][k], stride 66 -> conflict-free LDS.64 of k-pairs).
#define WT_STRIDE 66
__global__ __launch_bounds__(256) void k_gemm(const float* __restrict__ feature,
                                              const float* __restrict__ w_lin,
                                              const float* __restrict__ w_res,
                                              float* __restrict__ d_out) {
    __shared__ float sWT[128 * WT_STRIDE];  // [col][k] transposed, 33792B
    __shared__ float sF[32][64];            // [node][k], 8192B
    const float* __restrict__ W = (blockIdx.y == 0) ? w_lin : w_res;
    float* out = (blockIdx.y == 0) ? g_x : d_out;
    const int node0 = blockIdx.x * 32;
    const int warp = threadIdx.x >> 5;
    const int lane = threadIdx.x & 31;

    ull acc[4][4];
    #pragma unroll
    for (int a = 0; a < 4; a++)
        #pragma unroll
        for (int b = 0; b < 4; b++) acc[a][b] = 0ull;

    for (int kt = 0; kt < 2; kt++) {
        __syncthreads();
        // load W rows [kt*64 .. +64) x 128 cols, store transposed
        for (int i = threadIdx.x; i < 64 * 32; i += 256) {
            int kk = i >> 5, c4 = i & 31;
            float4 v = reinterpret_cast<const float4*>(W + (kt * 64 + kk) * 128)[c4];
            sWT[(4 * c4 + 0) * WT_STRIDE + kk] = v.x;
            sWT[(4 * c4 + 1) * WT_STRIDE + kk] = v.y;
            sWT[(4 * c4 + 2) * WT_STRIDE + kk] = v.z;
            sWT[(4 * c4 + 3) * WT_STRIDE + kk] = v.w;
        }
        // load feature chunk: 32 nodes x 64 k
        for (int i = threadIdx.x; i < 32 * 16; i += 256) {
            int n = i >> 4, c4 = i & 15;
            int node = node0 + n;
            float4 v = make_float4(0.f, 0.f, 0.f, 0.f);
            if (node < N_NODES)
                v = reinterpret_cast<const float4*>(feature + node * 128 + kt * 64)[c4];
            reinterpret_cast<float4*>(&sF[n][0])[c4] = v;
        }
        __syncthreads();
        #pragma unroll 8
        for (int k2 = 0; k2 < 32; k2++) {
            ull f0 = *reinterpret_cast<const ull*>(&sF[warp * 4 + 0][2 * k2]);
            ull f1 = *reinterpret_cast<const ull*>(&sF[warp * 4 + 1][2 * k2]);
            ull f2 = *reinterpret_cast<const ull*>(&sF[warp * 4 + 2][2 * k2]);
            ull f3 = *reinterpret_cast<const ull*>(&sF[warp * 4 + 3][2 * k2]);
            #pragma unroll
            for (int j = 0; j < 4; j++) {
                ull wp = *reinterpret_cast<const ull*>(
                    &sWT[(lane + 32 * j) * WT_STRIDE + 2 * k2]);
                acc[0][j] = fma2(f0, wp, acc[0][j]);
                acc[1][j] = fma2(f1, wp, acc[1][j]);
                acc[2][j] = fma2(f2, wp, acc[2][j]);
                acc[3][j] = fma2(f3, wp, acc[3][j]);
            }
        }
    }
    #pragma unroll
    for (int nn = 0; nn < 4; nn++) {
        int node = node0 + warp * 4 + nn;
        if (node < N_NODES) {
            #pragma unroll
            for (int j = 0; j < 4; j++) {
                float2 v = *reinterpret_cast<float2*>(&acc[nn][j]);
                out[node * 128 + lane + 32 * j] = v.x + v.y;
            }
        }
    }
}

// ---------------- per-node attention logits ----------------
__global__ void k_alar(const float* __restrict__ att_l, const float* __restrict__ att_r) {
    int id = blockIdx.x * blockDim.x + threadIdx.x;
    if (id >= N_NODES * NHEAD) return;
    int n = id >> 3, h = id & 7;
    const float4* xr = reinterpret_cast<const float4*>(g_x + n * 128 + h * 16);
    const float4* lp = reinterpret_cast<const float4*>(att_l + h * 16);
    const float4* rp = reinterpret_cast<const float4*>(att_r + h * 16);
    float sl = 0.f, sr = 0.f;
    #pragma unroll
    for (int c = 0; c < 4; c++) {
        float4 xv = xr[c], lv = lp[c], rv = rp[c];
        sl += xv.x * lv.x + xv.y * lv.y + xv.z * lv.z + xv.w * lv.w;
        sr += xv.x * rv.x + xv.y * rv.y + xv.z * rv.z + xv.w * rv.w;
    }
    g_al[id] = sl;
    g_ar[id] = sr;
}

// ---------------- histogram of dst (int4 vectorized) ----------------
__global__ void k_hist(const int* __restrict__ edst, int E) {
    int i = blockIdx.x * blockDim.x + threadIdx.x;
    if (i * 4 >= E) return;
    int4 d = reinterpret_cast<const int4*>(edst)[i];
    atomicAdd(&g_count[d.x], 1);
    atomicAdd(&g_count[d.y], 1);
    atomicAdd(&g_count[d.z], 1);
    atomicAdd(&g_count[d.w], 1);
}

// ---------------- single-block exclusive scan over 50K counts ----------------
__global__ __launch_bounds__(1024) void k_scan() {
    __shared__ int warp_sums[32];
    __shared__ int s_carry;
    int tid = threadIdx.x, lane = tid & 31, wid = tid >> 5;
    if (tid == 0) s_carry = 0;
    __syncthreads();
    for (int base = 0; base < N_NODES; base += 1024) {
        int i = base + tid;
        int v = (i < N_NODES) ? g_count[i] : 0;
        int incl = v;
        #pragma unroll
        for (int o = 1; o < 32; o <<= 1) {
            int t = __shfl_up_sync(0xFFFFFFFFu, incl, o);
            if (lane >= o) incl += t;
        }
        if (lane == 31) warp_sums[wid] = incl;
        __syncthreads();
        if (wid == 0) {
            int ws = warp_sums[lane];
            int wincl = ws;
            #pragma unroll
            for (int o = 1; o < 32; o <<= 1) {
                int t = __shfl_up_sync(0xFFFFFFFFu, wincl, o);
                if (lane >= o) wincl += t;
            }
            warp_sums[lane] = wincl - ws;   // exclusive warp prefix
        }
        __syncthreads();
        int excl = incl - v + warp_sums[wid] + s_carry;
        if (i < N_NODES) { g_rowptr[i] = excl; g_cursor[i] = excl; }
        __syncthreads();                     // all reads of s_carry/warp_sums done
        if (tid == 1023) s_carry += warp_sums[31] + incl;  // chunk total
        __syncthreads();
    }
    if (threadIdx.x == 0) g_rowptr[N_NODES] = s_carry;
}

// ---------------- scatter edges into dst-sorted order (x4) ----------------
__global__ void k_scatter(const int* __restrict__ esrc, const int* __restrict__ edst,
                          const float* __restrict__ ew, int E) {
    int i = blockIdx.x * blockDim.x + threadIdx.x;
    if (i * 4 >= E) return;
    int4 s = reinterpret_cast<const int4*>(esrc)[i];
    int4 d = reinterpret_cast<const int4*>(edst)[i];
    float4 w = reinterpret_cast<const float4*>(ew)[i];
    int p;
    p = atomicAdd(&g_cursor[d.x], 1); g_edge[p] = make_int2(s.x, __float_as_int(w.x));
    p = atomicAdd(&g_cursor[d.y], 1); g_edge[p] = make_int2(s.y, __float_as_int(w.y));
    p = atomicAdd(&g_cursor[d.z], 1); g_edge[p] = make_int2(s.z, __float_as_int(w.z));
    p = atomicAdd(&g_cursor[d.w], 1); g_edge[p] = make_int2(s.w, __float_as_int(w.w));
}

// ---------------- aggregate: one warp per dst node, fused finalize ----------------
__global__ __launch_bounds__(256) void k_agg(float* __restrict__ d_out) {
    int node = (blockIdx.x * blockDim.x + threadIdx.x) >> 5;
    if (node >= N_NODES) return;
    int lane = threadIdx.x & 31;
    int h = lane >> 2;                      // 4 lanes per head, 4 cols per lane
    int beg = __ldg(&g_rowptr[node]);
    int end = __ldg(&g_rowptr[node + 1]);
    float arv = g_ar[node * 8 + h];

    float a0 = 0.f, a1 = 0.f, a2 = 0.f, a3 = 0.f, dsum = 0.f;
    int e = beg;
    for (; e + 4 <= end; e += 4) {
        int2 ed[4];
        #pragma unroll
        for (int j = 0; j < 4; j++) ed[j] = __ldg(&g_edge[e + j]);
        float al[4];
        float4 xv[4];
        #pragma unroll
        for (int j = 0; j < 4; j++) {
            al[j] = __ldg(&g_al[ed[j].x * 8 + h]);
            xv[j] = __ldg(reinterpret_cast<const float4*>(g_x + ed[j].x * 128 + lane * 4));
        }
        #pragma unroll
        for (int j = 0; j < 4; j++) {
            float aa = __int_as_float(ed[j].y) * (al[j] + arv);
            aa = (aa > 0.f) ? aa : 0.2f * aa;
            float ee = __expf(aa);
            dsum += ee;
            a0 += ee * xv[j].x;
            a1 += ee * xv[j].y;
            a2 += ee * xv[j].z;
            a3 += ee * xv[j].w;
        }
    }
    for (; e < end; e++) {
        int2 e0 = __ldg(&g_edge[e]);
        float al0 = __ldg(&g_al[e0.x * 8 + h]);
        float4 x0 = __ldg(reinterpret_cast<const float4*>(g_x + e0.x * 128 + lane * 4));
        float aa0 = __int_as_float(e0.y) * (al0 + arv);
        aa0 = (aa0 > 0.f) ? aa0 : 0.2f * aa0;
        float ee0 = __expf(aa0);
        dsum += ee0;
        a0 += ee0 * x0.x; a1 += ee0 * x0.y; a2 += ee0 * x0.z; a3 += ee0 * x0.w;
    }

    float inv = (dsum > 0.f) ? 1.f / dsum : 0.f;
    float4 o = reinterpret_cast<float4*>(d_out)[node * 32 + lane];
    float v;
    v = a0 * inv; o.x += (v > 0.f) ? v : (__expf(v) - 1.f);
    v = a1 * inv; o.y += (v > 0.f) ? v : (__expf(v) - 1.f);
    v = a2 * inv; o.z += (v > 0.f) ? v : (__expf(v) - 1.f);
    v = a3 * inv; o.w += (v > 0.f) ? v : (__expf(v) - 1.f);
    reinterpret_cast<float4*>(d_out)[node * 32 + lane] = o;
}

extern "C" void kernel_launch(void* const* d_in, const int* in_sizes, int n_in,
                              void* d_out, int out_size) {
    const float* feature = (const float*)d_in[0];
    const int*   esrc    = (const int*)d_in[1];
    const int*   edst    = (const int*)d_in[2];
    const float* ew      = (const float*)d_in[3];
    const float* w_lin   = (const float*)d_in[4];
    const float* att_l   = (const float*)d_in[5];
    const float* att_r   = (const float*)d_in[6];
    const float* w_res   = (const float*)d_in[7];
    float* out = (float*)d_out;
    const int E = in_sizes[1];

    k_zero<<<(N_NODES + 255) / 256, 256>>>();

    dim3 gg((N_NODES + 31) / 32, 2);
    k_gemm<<<gg, 256>>>(feature, w_lin, w_res, out);

    k_alar<<<(N_NODES * NHEAD + 255) / 256, 256>>>(att_l, att_r);

    int e4 = E / 4;
    k_hist<<<(e4 + 255) / 256, 256>>>(edst, E);
    k_scan<<<1, 1024>>>();
    k_scatter<<<(e4 + 255) / 256, 256>>>(esrc, edst, ew, E);

    k_agg<<<(N_NODES * 32 + 255) / 256, 256>>>(out);
}

// round 5
// speedup vs baseline: 1.1062x; 1.1062x over previous
#include <cuda_runtime.h>
#include <cuda_fp16.h>

#define N_NODES 50000
#define N_EDGES 1600000
#define DIM 128
#define NHEAD 8

// ---- scratch (static device globals; no runtime allocation) ----
__device__ float  g_x[N_NODES * DIM];        // projected features [N,128] fp32
__device__ __half g_xh[N_NODES * DIM];       // fp16 mirror for the edge gather
__device__ float  g_al[N_NODES * NHEAD];     // left logits  [N,8]
__device__ float  g_ar[N_NODES * NHEAD];     // right logits [N,8]
__device__ int    g_count[N_NODES];          // per-dst edge counts
__device__ int    g_rowptr[N_NODES + 1];     // CSR row pointers
__device__ int    g_cursor[N_NODES];         // scatter cursors
__device__ int2   g_edge[N_EDGES];           // dst-sorted (src, weight_bits)

// ---------------- zero counters ----------------
__global__ void k_zero() {
    int i = blockIdx.x * blockDim.x + threadIdx.x;
    if (i < N_NODES) g_count[i] = 0;
}

// ---------------- fused dual GEMM: x = F@Wlin, res = F@Wres ----------------
// (round-3 scalar form — FFMA/crossbar balanced; f32x2 variant regressed)
__global__ __launch_bounds__(256) void k_gemm(const float* __restrict__ feature,
                                              const float* __restrict__ w_lin,
                                              const float* __restrict__ w_res,
                                              float* __restrict__ d_out) {
    __shared__ float sW[64][128];
    __shared__ float sF[32][64];
    const float* __restrict__ W = (blockIdx.y == 0) ? w_lin : w_res;
    float* out = (blockIdx.y == 0) ? g_x : d_out;
    const int node0 = blockIdx.x * 32;
    const int warp = threadIdx.x >> 5;
    const int lane = threadIdx.x & 31;

    float acc[4][4] = {};
    for (int kt = 0; kt < 2; kt++) {
        __syncthreads();
        for (int i = threadIdx.x; i < 64 * 32; i += 256) {
            int r = i >> 5, c4 = i & 31;
            float4 v = reinterpret_cast<const float4*>(W + (kt * 64 + r) * 128)[c4];
            reinterpret_cast<float4*>(&sW[r][0])[c4] = v;
        }
        for (int i = threadIdx.x; i < 32 * 16; i += 256) {
            int n = i >> 4, c4 = i & 15;
            int node = node0 + n;
            float4 v = make_float4(0.f, 0.f, 0.f, 0.f);
            if (node < N_NODES)
                v = reinterpret_cast<const float4*>(feature + node * 128 + kt * 64)[c4];
            reinterpret_cast<float4*>(&sF[n][0])[c4] = v;
        }
        __syncthreads();
        #pragma unroll 8
        for (int k = 0; k < 64; k++) {
            float f0 = sF[warp * 4 + 0][k];
            float f1 = sF[warp * 4 + 1][k];
            float f2 = sF[warp * 4 + 2][k];
            float f3 = sF[warp * 4 + 3][k];
            #pragma unroll
            for (int j = 0; j < 4; j++) {
                float wv = sW[k][lane + 32 * j];
                acc[0][j] += f0 * wv;
                acc[1][j] += f1 * wv;
                acc[2][j] += f2 * wv;
                acc[3][j] += f3 * wv;
            }
        }
    }
    const bool is_lin = (blockIdx.y == 0);
    #pragma unroll
    for (int nn = 0; nn < 4; nn++) {
        int node = node0 + warp * 4 + nn;
        if (node < N_NODES) {
            #pragma unroll
            for (int j = 0; j < 4; j++) {
                int col = lane + 32 * j;
                out[node * 128 + col] = acc[nn][j];
                if (is_lin) g_xh[node * 128 + col] = __float2half(acc[nn][j]);
            }
        }
    }
}

// ---------------- per-node attention logits (fp32 x) ----------------
__global__ void k_alar(const float* __restrict__ att_l, const float* __restrict__ att_r) {
    int id = blockIdx.x * blockDim.x + threadIdx.x;
    if (id >= N_NODES * NHEAD) return;
    int n = id >> 3, h = id & 7;
    const float4* xr = reinterpret_cast<const float4*>(g_x + n * 128 + h * 16);
    const float4* lp = reinterpret_cast<const float4*>(att_l + h * 16);
    const float4* rp = reinterpret_cast<const float4*>(att_r + h * 16);
    float sl = 0.f, sr = 0.f;
    #pragma unroll
    for (int c = 0; c < 4; c++) {
        float4 xv = xr[c], lv = lp[c], rv = rp[c];
        sl += xv.x * lv.x + xv.y * lv.y + xv.z * lv.z + xv.w * lv.w;
        sr += xv.x * rv.x + xv.y * rv.y + xv.z * rv.z + xv.w * rv.w;
    }
    g_al[id] = sl;
    g_ar[id] = sr;
}

// ---------------- histogram of dst (int4 vectorized) ----------------
__global__ void k_hist(const int* __restrict__ edst, int E) {
    int i = blockIdx.x * blockDim.x + threadIdx.x;
    if (i * 4 >= E) return;
    int4 d = reinterpret_cast<const int4*>(edst)[i];
    atomicAdd(&g_count[d.x], 1);
    atomicAdd(&g_count[d.y], 1);
    atomicAdd(&g_count[d.z], 1);
    atomicAdd(&g_count[d.w], 1);
}

// ---------------- single-block exclusive scan over 50K counts ----------------
__global__ __launch_bounds__(1024) void k_scan() {
    __shared__ int warp_sums[32];
    __shared__ int s_carry;
    int tid = threadIdx.x, lane = tid & 31, wid = tid >> 5;
    if (tid == 0) s_carry = 0;
    __syncthreads();
    for (int base = 0; base < N_NODES; base += 1024) {
        int i = base + tid;
        int v = (i < N_NODES) ? g_count[i] : 0;
        int incl = v;
        #pragma unroll
        for (int o = 1; o < 32; o <<= 1) {
            int t = __shfl_up_sync(0xFFFFFFFFu, incl, o);
            if (lane >= o) incl += t;
        }
        if (lane == 31) warp_sums[wid] = incl;
        __syncthreads();
        if (wid == 0) {
            int ws = warp_sums[lane];
            int wincl = ws;
            #pragma unroll
            for (int o = 1; o < 32; o <<= 1) {
                int t = __shfl_up_sync(0xFFFFFFFFu, wincl, o);
                if (lane >= o) wincl += t;
            }
            warp_sums[lane] = wincl - ws;   // exclusive warp prefix
        }
        __syncthreads();
        int excl = incl - v + warp_sums[wid] + s_carry;
        if (i < N_NODES) { g_rowptr[i] = excl; g_cursor[i] = excl; }
        __syncthreads();                     // all reads of s_carry/warp_sums done
        if (tid == 1023) s_carry += warp_sums[31] + incl;  // chunk total
        __syncthreads();
    }
    if (threadIdx.x == 0) g_rowptr[N_NODES] = s_carry;
}

// ---------------- scatter edges into dst-sorted order (x4) ----------------
__global__ void k_scatter(const int* __restrict__ esrc, const int* __restrict__ edst,
                          const float* __restrict__ ew, int E) {
    int i = blockIdx.x * blockDim.x + threadIdx.x;
    if (i * 4 >= E) return;
    int4 s = reinterpret_cast<const int4*>(esrc)[i];
    int4 d = reinterpret_cast<const int4*>(edst)[i];
    float4 w = reinterpret_cast<const float4*>(ew)[i];
    int p;
    p = atomicAdd(&g_cursor[d.x], 1); g_edge[p] = make_int2(s.x, __float_as_int(w.x));
    p = atomicAdd(&g_cursor[d.y], 1); g_edge[p] = make_int2(s.y, __float_as_int(w.y));
    p = atomicAdd(&g_cursor[d.z], 1); g_edge[p] = make_int2(s.z, __float_as_int(w.z));
    p = atomicAdd(&g_cursor[d.w], 1); g_edge[p] = make_int2(s.w, __float_as_int(w.w));
}

// ---------------- aggregate: one warp per dst node, fused finalize ----------------
// Gathers x in fp16 (256B/edge instead of 512B); coefs from fp32 logits.
__global__ __launch_bounds__(256) void k_agg(float* __restrict__ d_out) {
    int node = (blockIdx.x * blockDim.x + threadIdx.x) >> 5;
    if (node >= N_NODES) return;
    int lane = threadIdx.x & 31;
    int h = lane >> 2;                      // 4 lanes per head, 4 cols per lane
    int beg = __ldg(&g_rowptr[node]);
    int end = __ldg(&g_rowptr[node + 1]);
    float arv = g_ar[node * 8 + h];

    float a0 = 0.f, a1 = 0.f, a2 = 0.f, a3 = 0.f, dsum = 0.f;
    int e = beg;
    for (; e + 4 <= end; e += 4) {
        int2 ed[4];
        #pragma unroll
        for (int j = 0; j < 4; j++) ed[j] = __ldg(&g_edge[e + j]);
        float al[4];
        uint2 xh[4];
        #pragma unroll
        for (int j = 0; j < 4; j++) {
            al[j] = __ldg(&g_al[ed[j].x * 8 + h]);
            xh[j] = __ldg(reinterpret_cast<const uint2*>(g_xh + ed[j].x * 128) + lane);
        }
        #pragma unroll
        for (int j = 0; j < 4; j++) {
            float aa = __int_as_float(ed[j].y) * (al[j] + arv);
            aa = (aa > 0.f) ? aa : 0.2f * aa;
            float ee = __expf(aa);
            dsum += ee;
            float2 lo = __half22float2(*reinterpret_cast<const __half2*>(&xh[j].x));
            float2 hi = __half22float2(*reinterpret_cast<const __half2*>(&xh[j].y));
            a0 += ee * lo.x;
            a1 += ee * lo.y;
            a2 += ee * hi.x;
            a3 += ee * hi.y;
        }
    }
    for (; e < end; e++) {
        int2 e0 = __ldg(&g_edge[e]);
        float al0 = __ldg(&g_al[e0.x * 8 + h]);
        uint2 x0 = __ldg(reinterpret_cast<const uint2*>(g_xh + e0.x * 128) + lane);
        float aa0 = __int_as_float(e0.y) * (al0 + arv);
        aa0 = (aa0 > 0.f) ? aa0 : 0.2f * aa0;
        float ee0 = __expf(aa0);
        dsum += ee0;
        float2 lo = __half22float2(*reinterpret_cast<const __half2*>(&x0.x));
        float2 hi = __half22float2(*reinterpret_cast<const __half2*>(&x0.y));
        a0 += ee0 * lo.x; a1 += ee0 * lo.y; a2 += ee0 * hi.x; a3 += ee0 * hi.y;
    }

    float inv = (dsum > 0.f) ? 1.f / dsum : 0.f;
    float4 o = reinterpret_cast<float4*>(d_out)[node * 32 + lane];
    float v;
    v = a0 * inv; o.x += (v > 0.f) ? v : (__expf(v) - 1.f);
    v = a1 * inv; o.y += (v > 0.f) ? v : (__expf(v) - 1.f);
    v = a2 * inv; o.z += (v > 0.f) ? v : (__expf(v) - 1.f);
    v = a3 * inv; o.w += (v > 0.f) ? v : (__expf(v) - 1.f);
    reinterpret_cast<float4*>(d_out)[node * 32 + lane] = o;
}

extern "C" void kernel_launch(void* const* d_in, const int* in_sizes, int n_in,
                              void* d_out, int out_size) {
    const float* feature = (const float*)d_in[0];
    const int*   esrc    = (const int*)d_in[1];
    const int*   edst    = (const int*)d_in[2];
    const float* ew      = (const float*)d_in[3];
    const float* w_lin   = (const float*)d_in[4];
    const float* att_l   = (const float*)d_in[5];
    const float* att_r   = (const float*)d_in[6];
    const float* w_res   = (const float*)d_in[7];
    float* out = (float*)d_out;
    const int E = in_sizes[1];

    // Handles created once (host-side only; no device memory involved).
    static cudaStream_t s_side = nullptr;
    static cudaEvent_t ev_fork = nullptr, ev_join = nullptr;
    if (s_side == nullptr) {
        cudaStreamCreateWithFlags(&s_side, cudaStreamNonBlocking);
        cudaEventCreateWithFlags(&ev_fork, cudaEventDisableTiming);
        cudaEventCreateWithFlags(&ev_join, cudaEventDisableTiming);
    }

    const int e4 = E / 4;

    // Fork: CSR build (independent of GEMM) on side stream.
    cudaEventRecord(ev_fork, 0);
    cudaStreamWaitEvent(s_side, ev_fork, 0);
    k_zero<<<(N_NODES + 255) / 256, 256, 0, s_side>>>();
    k_hist<<<(e4 + 255) / 256, 256, 0, s_side>>>(edst, E);
    k_scan<<<1, 1024, 0, s_side>>>();
    k_scatter<<<(e4 + 255) / 256, 256, 0, s_side>>>(esrc, edst, ew, E);
    cudaEventRecord(ev_join, s_side);

    // Main chain: dual GEMM + logits.
    dim3 gg((N_NODES + 31) / 32, 2);
    k_gemm<<<gg, 256>>>(feature, w_lin, w_res, out);
    k_alar<<<(N_NODES * NHEAD + 255) / 256, 256>>>(att_l, att_r);

    // Join, then aggregate.
    cudaStreamWaitEvent(0, ev_join, 0);
    k_agg<<<(N_NODES * 32 + 255) / 256, 256>>>(out);
}

// round 7
// speedup vs baseline: 1.1694x; 1.0572x over previous
#include <cuda_runtime.h>
#include <cuda_fp16.h>

#define N_NODES 50000
#define N_EDGES 1600000
#define DIM 128
#define NHEAD 8

// ---- scratch (static device globals; no runtime allocation) ----
__device__ float  g_x[N_NODES * DIM];        // projected features [N,128] fp32
__device__ __half g_xh[N_NODES * DIM];       // fp16 mirror for the edge gather
__device__ float  g_al[N_NODES * NHEAD];     // left logits  [N,8]
__device__ float  g_ar[N_NODES * NHEAD];     // right logits [N,8]
__device__ int    g_count[N_NODES];          // per-dst edge counts
__device__ int    g_rowptr[N_NODES + 1];     // CSR row pointers
__device__ int    g_cursor[N_NODES];         // scatter cursors
__device__ int2   g_edge[N_EDGES];           // dst-sorted (src, weight_bits)

// ---------------- zero counters ----------------
__global__ void k_zero() {
    int i = blockIdx.x * blockDim.x + threadIdx.x;
    if (i < N_NODES) g_count[i] = 0;
}

// ---------------- fused dual GEMM + logits ----------------
// Lane owns 4 CONTIGUOUS cols [4*lane, 4*lane+4): inner loop is
// 1 LDS.128 (w) + 4 broadcast LDS.32 (f) + 16 FFMA per warp-k  ->  fma-bound.
// blockIdx.y==0: out=g_x (+ fp16 mirror + fused al/ar logits); ==1: residual.
__global__ __launch_bounds__(256) void k_gemm(const float* __restrict__ feature,
                                              const float* __restrict__ w_lin,
                                              const float* __restrict__ w_res,
                                              const float* __restrict__ att_l,
                                              const float* __restrict__ att_r,
                                              float* __restrict__ d_out) {
    __shared__ float sW[64][128];
    __shared__ float sF[32][64];
    const bool is_lin = (blockIdx.y == 0);
    const float* __restrict__ W = is_lin ? w_lin : w_res;
    float* out = is_lin ? g_x : d_out;
    const int node0 = blockIdx.x * 32;
    const int warp = threadIdx.x >> 5;
    const int lane = threadIdx.x & 31;

    float4 acc[4];
    #pragma unroll
    for (int nn = 0; nn < 4; nn++) acc[nn] = make_float4(0.f, 0.f, 0.f, 0.f);

    for (int kt = 0; kt < 2; kt++) {
        __syncthreads();
        for (int i = threadIdx.x; i < 64 * 32; i += 256) {
            int r = i >> 5, c4 = i & 31;
            float4 v = reinterpret_cast<const float4*>(W + (kt * 64 + r) * 128)[c4];
            reinterpret_cast<float4*>(&sW[r][0])[c4] = v;
        }
        for (int i = threadIdx.x; i < 32 * 16; i += 256) {
            int n = i >> 4, c4 = i & 15;
            int node = node0 + n;
            float4 v = make_float4(0.f, 0.f, 0.f, 0.f);
            if (node < N_NODES)
                v = reinterpret_cast<const float4*>(feature + node * 128 + kt * 64)[c4];
            reinterpret_cast<float4*>(&sF[n][0])[c4] = v;
        }
        __syncthreads();
        #pragma unroll 8
        for (int k = 0; k < 64; k++) {
            float4 w4 = *reinterpret_cast<const float4*>(&sW[k][lane * 4]);
            float f0 = sF[warp * 4 + 0][k];
            float f1 = sF[warp * 4 + 1][k];
            float f2 = sF[warp * 4 + 2][k];
            float f3 = sF[warp * 4 + 3][k];
            acc[0].x += f0 * w4.x; acc[0].y += f0 * w4.y;
            acc[0].z += f0 * w4.z; acc[0].w += f0 * w4.w;
            acc[1].x += f1 * w4.x; acc[1].y += f1 * w4.y;
            acc[1].z += f1 * w4.z; acc[1].w += f1 * w4.w;
            acc[2].x += f2 * w4.x; acc[2].y += f2 * w4.y;
            acc[2].z += f2 * w4.z; acc[2].w += f2 * w4.w;
            acc[3].x += f3 * w4.x; acc[3].y += f3 * w4.y;
            acc[3].z += f3 * w4.z; acc[3].w += f3 * w4.w;
        }
    }

    // epilogue
    const int h = lane >> 2;                 // head of this lane's 4 cols
    float4 la = make_float4(0.f, 0.f, 0.f, 0.f), ra = la;
    if (is_lin) {
        la = reinterpret_cast<const float4*>(att_l)[h * 4 + (lane & 3)];
        ra = reinterpret_cast<const float4*>(att_r)[h * 4 + (lane & 3)];
    }
    #pragma unroll
    for (int nn = 0; nn < 4; nn++) {
        int node = node0 + warp * 4 + nn;
        bool ok = (node < N_NODES);          // uniform across warp
        if (ok)
            reinterpret_cast<float4*>(out + node * 128)[lane] = acc[nn];
        if (is_lin) {
            float sl = acc[nn].x * la.x + acc[nn].y * la.y + acc[nn].z * la.z + acc[nn].w * la.w;
            float sr = acc[nn].x * ra.x + acc[nn].y * ra.y + acc[nn].z * ra.z + acc[nn].w * ra.w;
            sl += __shfl_xor_sync(0xFFFFFFFFu, sl, 1);
            sl += __shfl_xor_sync(0xFFFFFFFFu, sl, 2);
            sr += __shfl_xor_sync(0xFFFFFFFFu, sr, 1);
            sr += __shfl_xor_sync(0xFFFFFFFFu, sr, 2);
            if (ok) {
                __half2 h0 = __floats2half2_rn(acc[nn].x, acc[nn].y);
                __half2 h1 = __floats2half2_rn(acc[nn].z, acc[nn].w);
                uint2 packed;
                packed.x = *reinterpret_cast<unsigned*>(&h0);
                packed.y = *reinterpret_cast<unsigned*>(&h1);
                reinterpret_cast<uint2*>(g_xh + node * 128)[lane] = packed;
                if ((lane & 3) == 0) {
                    g_al[node * 8 + h] = sl;
                    g_ar[node * 8 + h] = sr;
                }
            }
        }
    }
}

// ---------------- histogram of dst (int4 vectorized) ----------------
__global__ void k_hist(const int* __restrict__ edst, int E) {
    int i = blockIdx.x * blockDim.x + threadIdx.x;
    if (i * 4 >= E) return;
    int4 d = reinterpret_cast<const int4*>(edst)[i];
    atomicAdd(&g_count[d.x], 1);
    atomicAdd(&g_count[d.y], 1);
    atomicAdd(&g_count[d.z], 1);
    atomicAdd(&g_count[d.w], 1);
}

// ---------------- single-block exclusive scan over 50K counts ----------------
__global__ __launch_bounds__(1024) void k_scan() {
    __shared__ int warp_sums[32];
    __shared__ int s_carry;
    int tid = threadIdx.x, lane = tid & 31, wid = tid >> 5;
    if (tid == 0) s_carry = 0;
    __syncthreads();
    for (int base = 0; base < N_NODES; base += 1024) {
        int i = base + tid;
        int v = (i < N_NODES) ? g_count[i] : 0;
        int incl = v;
        #pragma unroll
        for (int o = 1; o < 32; o <<= 1) {
            int t = __shfl_up_sync(0xFFFFFFFFu, incl, o);
            if (lane >= o) incl += t;
        }
        if (lane == 31) warp_sums[wid] = incl;
        __syncthreads();
        if (wid == 0) {
            int ws = warp_sums[lane];
            int wincl = ws;
            #pragma unroll
            for (int o = 1; o < 32; o <<= 1) {
                int t = __shfl_up_sync(0xFFFFFFFFu, wincl, o);
                if (lane >= o) wincl += t;
            }
            warp_sums[lane] = wincl - ws;   // exclusive warp prefix
        }
        __syncthreads();
        int excl = incl - v + warp_sums[wid] + s_carry;
        if (i < N_NODES) { g_rowptr[i] = excl; g_cursor[i] = excl; }
        __syncthreads();                     // all reads of s_carry/warp_sums done
        if (tid == 1023) s_carry += warp_sums[31] + incl;  // chunk total
        __syncthreads();
    }
    if (threadIdx.x == 0) g_rowptr[N_NODES] = s_carry;
}

// ---------------- scatter edges into dst-sorted order (x4) ----------------
__global__ void k_scatter(const int* __restrict__ esrc, const int* __restrict__ edst,
                          const float* __restrict__ ew, int E) {
    int i = blockIdx.x * blockDim.x + threadIdx.x;
    if (i * 4 >= E) return;
    int4 s = reinterpret_cast<const int4*>(esrc)[i];
    int4 d = reinterpret_cast<const int4*>(edst)[i];
    float4 w = reinterpret_cast<const float4*>(ew)[i];
    int p;
    p = atomicAdd(&g_cursor[d.x], 1); g_edge[p] = make_int2(s.x, __float_as_int(w.x));
    p = atomicAdd(&g_cursor[d.y], 1); g_edge[p] = make_int2(s.y, __float_as_int(w.y));
    p = atomicAdd(&g_cursor[d.z], 1); g_edge[p] = make_int2(s.z, __float_as_int(w.z));
    p = atomicAdd(&g_cursor[d.w], 1); g_edge[p] = make_int2(s.w, __float_as_int(w.w));
}

// ---------------- aggregate: one warp per dst node, fused finalize ----------------
// Gathers x in fp16 (256B/edge); coefs from fp32 logits.
__global__ __launch_bounds__(256) void k_agg(float* __restrict__ d_out) {
    int node = (blockIdx.x * blockDim.x + threadIdx.x) >> 5;
    if (node >= N_NODES) return;
    int lane = threadIdx.x & 31;
    int h = lane >> 2;                      // 4 lanes per head, 4 cols per lane
    int beg = __ldg(&g_rowptr[node]);
    int end = __ldg(&g_rowptr[node + 1]);
    float arv = g_ar[node * 8 + h];

    float a0 = 0.f, a1 = 0.f, a2 = 0.f, a3 = 0.f, dsum = 0.f;
    int e = beg;
    for (; e + 4 <= end; e += 4) {
        int2 ed[4];
        #pragma unroll
        for (int j = 0; j < 4; j++) ed[j] = __ldg(&g_edge[e + j]);
        float al[4];
        uint2 xh[4];
        #pragma unroll
        for (int j = 0; j < 4; j++) {
            al[j] = __ldg(&g_al[ed[j].x * 8 + h]);
            xh[j] = __ldg(reinterpret_cast<const uint2*>(g_xh + ed[j].x * 128) + lane);
        }
        #pragma unroll
        for (int j = 0; j < 4; j++) {
            float aa = __int_as_float(ed[j].y) * (al[j] + arv);
            aa = (aa > 0.f) ? aa : 0.2f * aa;
            float ee = __expf(aa);
            dsum += ee;
            float2 lo = __half22float2(*reinterpret_cast<const __half2*>(&xh[j].x));
            float2 hi = __half22float2(*reinterpret_cast<const __half2*>(&xh[j].y));
            a0 += ee * lo.x;
            a1 += ee * lo.y;
            a2 += ee * hi.x;
            a3 += ee * hi.y;
        }
    }
    for (; e < end; e++) {
        int2 e0 = __ldg(&g_edge[e]);
        float al0 = __ldg(&g_al[e0.x * 8 + h]);
        uint2 x0 = __ldg(reinterpret_cast<const uint2*>(g_xh + e0.x * 128) + lane);
        float aa0 = __int_as_float(e0.y) * (al0 + arv);
        aa0 = (aa0 > 0.f) ? aa0 : 0.2f * aa0;
        float ee0 = __expf(aa0);
        dsum += ee0;
        float2 lo = __half22float2(*reinterpret_cast<const __half2*>(&x0.x));
        float2 hi = __half22float2(*reinterpret_cast<const __half2*>(&x0.y));
        a0 += ee0 * lo.x; a1 += ee0 * lo.y; a2 += ee0 * hi.x; a3 += ee0 * hi.y;
    }

    float inv = (dsum > 0.f) ? 1.f / dsum : 0.f;
    float4 o = reinterpret_cast<float4*>(d_out)[node * 32 + lane];
    float v;
    v = a0 * inv; o.x += (v > 0.f) ? v : (__expf(v) - 1.f);
    v = a1 * inv; o.y += (v > 0.f) ? v : (__expf(v) - 1.f);
    v = a2 * inv; o.z += (v > 0.f) ? v : (__expf(v) - 1.f);
    v = a3 * inv; o.w += (v > 0.f) ? v : (__expf(v) - 1.f);
    reinterpret_cast<float4*>(d_out)[node * 32 + lane] = o;
}

extern "C" void kernel_launch(void* const* d_in, const int* in_sizes, int n_in,
                              void* d_out, int out_size) {
    const float* feature = (const float*)d_in[0];
    const int*   esrc    = (const int*)d_in[1];
    const int*   edst    = (const int*)d_in[2];
    const float* ew      = (const float*)d_in[3];
    const float* w_lin   = (const float*)d_in[4];
    const float* att_l   = (const float*)d_in[5];
    const float* att_r   = (const float*)d_in[6];
    const float* w_res   = (const float*)d_in[7];
    float* out = (float*)d_out;
    const int E = in_sizes[1];

    static cudaStream_t s_side = nullptr;
    static cudaEvent_t ev_fork = nullptr, ev_join = nullptr;
    if (s_side == nullptr) {
        cudaStreamCreateWithFlags(&s_side, cudaStreamNonBlocking);
        cudaEventCreateWithFlags(&ev_fork, cudaEventDisableTiming);
        cudaEventCreateWithFlags(&ev_join, cudaEventDisableTiming);
    }

    const int e4 = E / 4;

    // Fork: CSR build on side stream. Issue zero/hist/scan first so k_gemm is
    // the 4th kernel issued (profiler samples launch #4 of ours).
    cudaEventRecord(ev_fork, 0);
    cudaStreamWaitEvent(s_side, ev_fork, 0);
    k_zero<<<(N_NODES + 255) / 256, 256, 0, s_side>>>();
    k_hist<<<(e4 + 255) / 256, 256, 0, s_side>>>(edst, E);
    k_scan<<<1, 1024, 0, s_side>>>();

    // Main chain: fused dual GEMM + logits (4th issue -> profiled).
    dim3 gg((N_NODES + 31) / 32, 2);
    k_gemm<<<gg, 256>>>(feature, w_lin, w_res, att_l, att_r, out);

    k_scatter<<<(e4 + 255) / 256, 256, 0, s_side>>>(esrc, edst, ew, E);
    cudaEventRecord(ev_join, s_side);

    cudaStreamWaitEvent(0, ev_join, 0);
    k_agg<<<(N_NODES * 32 + 255) / 256, 256>>>(out);
}

// round 8
// speedup vs baseline: 1.1791x; 1.0083x over previous
#include <cuda_runtime.h>
#include <cuda_fp16.h>

#define N_NODES 50000
#define N_EDGES 1600000
#define DIM 128
#define NHEAD 8

// ---- scratch (static device globals; no runtime allocation) ----
__device__ float  g_x[N_NODES * DIM];        // projected features [N,128] fp32
__device__ __half g_xh[N_NODES * DIM];       // fp16 mirror for the edge gather
__device__ float  g_al[N_NODES * NHEAD];     // left logits  [N,8]
__device__ float  g_ar[N_NODES * NHEAD];     // right logits [N,8]
__device__ int    g_count[N_NODES];          // per-dst edge counts
__device__ int    g_rowptr[N_NODES + 1];     // CSR row pointers
__device__ int    g_cursor[N_NODES];         // scatter cursors
__device__ int2   g_edge[N_EDGES];           // dst-sorted (src, weight_bits)

// ---------------- zero counters ----------------
__global__ void k_zero() {
    int i = blockIdx.x * blockDim.x + threadIdx.x;
    if (i < N_NODES) g_count[i] = 0;
}

// ---------------- fused dual GEMM + logits, 2D register tiling ----------------
// Block tile: 64 nodes x 128 cols. 256 thr = 32(tx: col-groups of 4) x 8(ty:
// node-groups of 8). Thread tile 8 nodes x 4 cols = 32 acc.
// Per thread-k: 1 LDS.128 (w, distinct) + 2 LDS.128 (f, warp-broadcast) + 32 FFMA
// -> per warp-k 6 smem phases vs 16 fma cycles: FMA-bound.
__global__ __launch_bounds__(256) void k_gemm(const float* __restrict__ feature,
                                              const float* __restrict__ w_lin,
                                              const float* __restrict__ w_res,
                                              const float* __restrict__ att_l,
                                              const float* __restrict__ att_r,
                                              float* __restrict__ d_out) {
    __shared__ float sW[64][128];      // [k][col]   32KB
    __shared__ float sFt[64][64];      // [k][node]  16KB (transposed)
    const bool is_lin = (blockIdx.y == 0);
    const float* __restrict__ W = is_lin ? w_lin : w_res;
    float* out = is_lin ? g_x : d_out;
    const int node0 = blockIdx.x * 64;
    const int tx = threadIdx.x & 31;   // col group: cols [4tx, 4tx+4)
    const int ty = threadIdx.x >> 5;   // node group: nodes [8ty, 8ty+8)

    float4 acc[8];
    #pragma unroll
    for (int nn = 0; nn < 8; nn++) acc[nn] = make_float4(0.f, 0.f, 0.f, 0.f);

    for (int kt = 0; kt < 2; kt++) {
        __syncthreads();
        // W chunk: rows [kt*64, +64) x 128 cols
        for (int i = threadIdx.x; i < 64 * 32; i += 256) {
            int r = i >> 5, c4 = i & 31;
            float4 v = reinterpret_cast<const float4*>(W + (kt * 64 + r) * 128)[c4];
            reinterpret_cast<float4*>(&sW[r][0])[c4] = v;
        }
        // F chunk, stored transposed: sFt[k][node]
        for (int i = threadIdx.x; i < 64 * 16; i += 256) {
            int node = i & 63, kq = i >> 6;           // kq in [0,16)
            int gnode = node0 + node;
            float4 v = make_float4(0.f, 0.f, 0.f, 0.f);
            if (gnode < N_NODES)
                v = reinterpret_cast<const float4*>(feature + gnode * 128 + kt * 64)[kq];
            sFt[kq * 4 + 0][node] = v.x;
            sFt[kq * 4 + 1][node] = v.y;
            sFt[kq * 4 + 2][node] = v.z;
            sFt[kq * 4 + 3][node] = v.w;
        }
        __syncthreads();
        #pragma unroll 8
        for (int k = 0; k < 64; k++) {
            float4 w4 = *reinterpret_cast<const float4*>(&sW[k][tx * 4]);
            float4 fA = *reinterpret_cast<const float4*>(&sFt[k][ty * 8]);
            float4 fB = *reinterpret_cast<const float4*>(&sFt[k][ty * 8 + 4]);
            acc[0].x += fA.x * w4.x; acc[0].y += fA.x * w4.y; acc[0].z += fA.x * w4.z; acc[0].w += fA.x * w4.w;
            acc[1].x += fA.y * w4.x; acc[1].y += fA.y * w4.y; acc[1].z += fA.y * w4.z; acc[1].w += fA.y * w4.w;
            acc[2].x += fA.z * w4.x; acc[2].y += fA.z * w4.y; acc[2].z += fA.z * w4.z; acc[2].w += fA.z * w4.w;
            acc[3].x += fA.w * w4.x; acc[3].y += fA.w * w4.y; acc[3].z += fA.w * w4.z; acc[3].w += fA.w * w4.w;
            acc[4].x += fB.x * w4.x; acc[4].y += fB.x * w4.y; acc[4].z += fB.x * w4.z; acc[4].w += fB.x * w4.w;
            acc[5].x += fB.y * w4.x; acc[5].y += fB.y * w4.y; acc[5].z += fB.y * w4.z; acc[5].w += fB.y * w4.w;
            acc[6].x += fB.z * w4.x; acc[6].y += fB.z * w4.y; acc[6].z += fB.z * w4.z; acc[6].w += fB.z * w4.w;
            acc[7].x += fB.w * w4.x; acc[7].y += fB.w * w4.y; acc[7].z += fB.w * w4.z; acc[7].w += fB.w * w4.w;
        }
    }

    // epilogue: cols [4tx,4tx+4) lie in head h = tx>>2; att flat index = tx.
    const int h = tx >> 2;
    float4 la = make_float4(0.f, 0.f, 0.f, 0.f), ra = la;
    if (is_lin) {
        la = reinterpret_cast<const float4*>(att_l)[tx];
        ra = reinterpret_cast<const float4*>(att_r)[tx];
    }
    #pragma unroll
    for (int nn = 0; nn < 8; nn++) {
        int node = node0 + ty * 8 + nn;
        bool ok = (node < N_NODES);
        if (ok)
            reinterpret_cast<float4*>(out + node * 128)[tx] = acc[nn];
        if (is_lin) {
            float sl = acc[nn].x * la.x + acc[nn].y * la.y + acc[nn].z * la.z + acc[nn].w * la.w;
            float sr = acc[nn].x * ra.x + acc[nn].y * ra.y + acc[nn].z * ra.z + acc[nn].w * ra.w;
            sl += __shfl_xor_sync(0xFFFFFFFFu, sl, 1);
            sl += __shfl_xor_sync(0xFFFFFFFFu, sl, 2);
            sr += __shfl_xor_sync(0xFFFFFFFFu, sr, 1);
            sr += __shfl_xor_sync(0xFFFFFFFFu, sr, 2);
            if (ok) {
                __half2 h0 = __floats2half2_rn(acc[nn].x, acc[nn].y);
                __half2 h1 = __floats2half2_rn(acc[nn].z, acc[nn].w);
                uint2 packed;
                packed.x = *reinterpret_cast<unsigned*>(&h0);
                packed.y = *reinterpret_cast<unsigned*>(&h1);
                reinterpret_cast<uint2*>(g_xh + node * 128)[tx] = packed;
                if ((tx & 3) == 0) {
                    g_al[node * 8 + h] = sl;
                    g_ar[node * 8 + h] = sr;
                }
            }
        }
    }
}

// ---------------- histogram of dst (int4 vectorized) ----------------
__global__ void k_hist(const int* __restrict__ edst, int E) {
    int i = blockIdx.x * blockDim.x + threadIdx.x;
    if (i * 4 >= E) return;
    int4 d = reinterpret_cast<const int4*>(edst)[i];
    atomicAdd(&g_count[d.x], 1);
    atomicAdd(&g_count[d.y], 1);
    atomicAdd(&g_count[d.z], 1);
    atomicAdd(&g_count[d.w], 1);
}

// ---------------- single-block exclusive scan over 50K counts ----------------
__global__ __launch_bounds__(1024) void k_scan() {
    __shared__ int warp_sums[32];
    __shared__ int s_carry;
    int tid = threadIdx.x, lane = tid & 31, wid = tid >> 5;
    if (tid == 0) s_carry = 0;
    __syncthreads();
    for (int base = 0; base < N_NODES; base += 1024) {
        int i = base + tid;
        int v = (i < N_NODES) ? g_count[i] : 0;
        int incl = v;
        #pragma unroll
        for (int o = 1; o < 32; o <<= 1) {
            int t = __shfl_up_sync(0xFFFFFFFFu, incl, o);
            if (lane >= o) incl += t;
        }
        if (lane == 31) warp_sums[wid] = incl;
        __syncthreads();
        if (wid == 0) {
            int ws = warp_sums[lane];
            int wincl = ws;
            #pragma unroll
            for (int o = 1; o < 32; o <<= 1) {
                int t = __shfl_up_sync(0xFFFFFFFFu, wincl, o);
                if (lane >= o) wincl += t;
            }
            warp_sums[lane] = wincl - ws;   // exclusive warp prefix
        }
        __syncthreads();
        int excl = incl - v + warp_sums[wid] + s_carry;
        if (i < N_NODES) { g_rowptr[i] = excl; g_cursor[i] = excl; }
        __syncthreads();                     // all reads of s_carry/warp_sums done
        if (tid == 1023) s_carry += warp_sums[31] + incl;  // chunk total
        __syncthreads();
    }
    if (threadIdx.x == 0) g_rowptr[N_NODES] = s_carry;
}

// ---------------- scatter edges into dst-sorted order (x4) ----------------
__global__ void k_scatter(const int* __restrict__ esrc, const int* __restrict__ edst,
                          const float* __restrict__ ew, int E) {
    int i = blockIdx.x * blockDim.x + threadIdx.x;
    if (i * 4 >= E) return;
    int4 s = reinterpret_cast<const int4*>(esrc)[i];
    int4 d = reinterpret_cast<const int4*>(edst)[i];
    float4 w = reinterpret_cast<const float4*>(ew)[i];
    int p;
    p = atomicAdd(&g_cursor[d.x], 1); g_edge[p] = make_int2(s.x, __float_as_int(w.x));
    p = atomicAdd(&g_cursor[d.y], 1); g_edge[p] = make_int2(s.y, __float_as_int(w.y));
    p = atomicAdd(&g_cursor[d.z], 1); g_edge[p] = make_int2(s.z, __float_as_int(w.z));
    p = atomicAdd(&g_cursor[d.w], 1); g_edge[p] = make_int2(s.w, __float_as_int(w.w));
}

// ---------------- aggregate: one warp per dst node, fused finalize ----------------
// Gathers x in fp16 (256B/edge); coefs from fp32 logits.
__global__ __launch_bounds__(256) void k_agg(float* __restrict__ d_out) {
    int node = (blockIdx.x * blockDim.x + threadIdx.x) >> 5;
    if (node >= N_NODES) return;
    int lane = threadIdx.x & 31;
    int h = lane >> 2;                      // 4 lanes per head, 4 cols per lane
    int beg = __ldg(&g_rowptr[node]);
    int end = __ldg(&g_rowptr[node + 1]);
    float arv = g_ar[node * 8 + h];

    float a0 = 0.f, a1 = 0.f, a2 = 0.f, a3 = 0.f, dsum = 0.f;
    int e = beg;
    for (; e + 4 <= end; e += 4) {
        int2 ed[4];
        #pragma unroll
        for (int j = 0; j < 4; j++) ed[j] = __ldg(&g_edge[e + j]);
        float al[4];
        uint2 xh[4];
        #pragma unroll
        for (int j = 0; j < 4; j++) {
            al[j] = __ldg(&g_al[ed[j].x * 8 + h]);
            xh[j] = __ldg(reinterpret_cast<const uint2*>(g_xh + ed[j].x * 128) + lane);
        }
        #pragma unroll
        for (int j = 0; j < 4; j++) {
            float aa = __int_as_float(ed[j].y) * (al[j] + arv);
            aa = (aa > 0.f) ? aa : 0.2f * aa;
            float ee = __expf(aa);
            dsum += ee;
            float2 lo = __half22float2(*reinterpret_cast<const __half2*>(&xh[j].x));
            float2 hi = __half22float2(*reinterpret_cast<const __half2*>(&xh[j].y));
            a0 += ee * lo.x;
            a1 += ee * lo.y;
            a2 += ee * hi.x;
            a3 += ee * hi.y;
        }
    }
    for (; e < end; e++) {
        int2 e0 = __ldg(&g_edge[e]);
        float al0 = __ldg(&g_al[e0.x * 8 + h]);
        uint2 x0 = __ldg(reinterpret_cast<const uint2*>(g_xh + e0.x * 128) + lane);
        float aa0 = __int_as_float(e0.y) * (al0 + arv);
        aa0 = (aa0 > 0.f) ? aa0 : 0.2f * aa0;
        float ee0 = __expf(aa0);
        dsum += ee0;
        float2 lo = __half22float2(*reinterpret_cast<const __half2*>(&x0.x));
        float2 hi = __half22float2(*reinterpret_cast<const __half2*>(&x0.y));
        a0 += ee0 * lo.x; a1 += ee0 * lo.y; a2 += ee0 * hi.x; a3 += ee0 * hi.y;
    }

    float inv = (dsum > 0.f) ? 1.f / dsum : 0.f;
    float4 o = reinterpret_cast<float4*>(d_out)[node * 32 + lane];
    float v;
    v = a0 * inv; o.x += (v > 0.f) ? v : (__expf(v) - 1.f);
    v = a1 * inv; o.y += (v > 0.f) ? v : (__expf(v) - 1.f);
    v = a2 * inv; o.z += (v > 0.f) ? v : (__expf(v) - 1.f);
    v = a3 * inv; o.w += (v > 0.f) ? v : (__expf(v) - 1.f);
    reinterpret_cast<float4*>(d_out)[node * 32 + lane] = o;
}

extern "C" void kernel_launch(void* const* d_in, const int* in_sizes, int n_in,
                              void* d_out, int out_size) {
    const float* feature = (const float*)d_in[0];
    const int*   esrc    = (const int*)d_in[1];
    const int*   edst    = (const int*)d_in[2];
    const float* ew      = (const float*)d_in[3];
    const float* w_lin   = (const float*)d_in[4];
    const float* att_l   = (const float*)d_in[5];
    const float* att_r   = (const float*)d_in[6];
    const float* w_res   = (const float*)d_in[7];
    float* out = (float*)d_out;
    const int E = in_sizes[1];

    static cudaStream_t s_side = nullptr;
    static cudaEvent_t ev_fork = nullptr, ev_join = nullptr;
    if (s_side == nullptr) {
        cudaStreamCreateWithFlags(&s_side, cudaStreamNonBlocking);
        cudaEventCreateWithFlags(&ev_fork, cudaEventDisableTiming);
        cudaEventCreateWithFlags(&ev_join, cudaEventDisableTiming);
    }

    const int e4 = E / 4;

    // Fork: CSR build on side stream; k_gemm stays the 4th issued (profiled).
    cudaEventRecord(ev_fork, 0);
    cudaStreamWaitEvent(s_side, ev_fork, 0);
    k_zero<<<(N_NODES + 255) / 256, 256, 0, s_side>>>();
    k_hist<<<(e4 + 255) / 256, 256, 0, s_side>>>(edst, E);
    k_scan<<<1, 1024, 0, s_side>>>();

    dim3 gg((N_NODES + 63) / 64, 2);
    k_gemm<<<gg, 256>>>(feature, w_lin, w_res, att_l, att_r, out);

    k_scatter<<<(e4 + 255) / 256, 256, 0, s_side>>>(esrc, edst, ew, E);
    cudaEventRecord(ev_join, s_side);

    cudaStreamWaitEvent(0, ev_join, 0);
    k_agg<<<(N_NODES * 32 + 255) / 256, 256>>>(out);
}

// round 11
// speedup vs baseline: 1.4119x; 1.1975x over previous
#include <cuda_runtime.h>
#include <cuda_fp16.h>
#include <cuda_bf16.h>
#include <cstdint>

#define N_NODES 50000
#define N_EDGES 1600000
#define DIM 128
#define NHEAD 8

// ---- scratch (static device globals; no runtime allocation) ----
__device__ __half g_xh[N_NODES * DIM];       // fp16 projected features (edge gather)
__device__ float  g_al[N_NODES * NHEAD];     // left logits  [N,8]
__device__ float  g_ar[N_NODES * NHEAD];     // right logits [N,8]
__device__ int    g_count[N_NODES];          // per-dst edge counts
__device__ int    g_rowptr[N_NODES + 1];     // CSR row pointers
__device__ int    g_cursor[N_NODES];         // scatter cursors
__device__ int2   g_edge[N_EDGES];           // dst-sorted (src, weight_bits)

__device__ __forceinline__ uint32_t smem_u32(const void* p) {
    uint32_t a;
    asm("{ .reg .u64 t; cvta.to.shared.u64 t, %1; cvt.u32.u64 %0, t; }" : "=r"(a) : "l"(p));
    return a;
}
__device__ __forceinline__ void ldsm4(uint32_t* r, uint32_t addr) {
    asm volatile("ldmatrix.sync.aligned.m8n8.x4.shared.b16 {%0,%1,%2,%3}, [%4];"
                 : "=r"(r[0]), "=r"(r[1]), "=r"(r[2]), "=r"(r[3]) : "r"(addr));
}
__device__ __forceinline__ void ldsm4t(uint32_t* r, uint32_t addr) {
    asm volatile("ldmatrix.sync.aligned.m8n8.x4.trans.shared.b16 {%0,%1,%2,%3}, [%4];"
                 : "=r"(r[0]), "=r"(r[1]), "=r"(r[2]), "=r"(r[3]) : "r"(addr));
}
__device__ __forceinline__ void mma16816(float* c, const uint32_t* a, const uint32_t* b) {
    asm volatile("mma.sync.aligned.m16n8k16.row.col.f32.bf16.bf16.f32 "
                 "{%0,%1,%2,%3}, {%4,%5,%6,%7}, {%8,%9}, {%0,%1,%2,%3};"
                 : "+f"(c[0]), "+f"(c[1]), "+f"(c[2]), "+f"(c[3])
                 : "r"(a[0]), "r"(a[1]), "r"(a[2]), "r"(a[3]), "r"(b[0]), "r"(b[1]));
}

// smem tile strides (bf16 units): pad rows to 136 (272B = 17*16B -> ldmatrix
// row addresses conflict-free: 272 mod 128 = 16, distinct quadrants per 8 rows)
#define APAD 136
// smem layout (bytes)
#define SM_ATT 0                            // 256 floats (att_l | att_r)
#define SM_AH  1024
#define SM_AL  (SM_AH + 64 * APAD * 2)      // 18432
#define SM_BH  (SM_AL + 64 * APAD * 2)      // 35840
#define SM_BL  (SM_BH + 128 * APAD * 2)     // 70656
#define SM_TOT (SM_BL + 128 * APAD * 2)     // 105472

// ---------------- zero counters ----------------
__global__ void k_zero() {
    int i = blockIdx.x * blockDim.x + threadIdx.x;
    if (i < N_NODES) g_count[i] = 0;
}

// ========== bf16 split-precision mma.sync GEMM + fused logits/mirror ==========
// CTA: 64 nodes x 128 cols. blockIdx.y: 0 -> x (=F@Wlin) epilogue (fp16 mirror
// + logits), 1 -> residual (=F@Wres) -> d_out.
// D = A_hi@B_hi + A_lo@B_hi + A_hi@B_lo  (fp32 register accumulators).
__global__ __launch_bounds__(256) void k_gemm(const float* __restrict__ feature,
                                              const float* __restrict__ w_lin,
                                              const float* __restrict__ w_res,
                                              const float* __restrict__ att_l,
                                              const float* __restrict__ att_r,
                                              float* __restrict__ d_out) {
    extern __shared__ char smem[];
    const uint32_t sb = smem_u32(smem);
    const int tid = threadIdx.x;
    const int lane = tid & 31;
    const int w = tid >> 5;
    const int wm = w >> 2;                  // 0..1: nodes [32wm, 32wm+32)
    const int wn = w & 3;                   // 0..3: cols  [32wn, 32wn+32)
    const bool is_lin = (blockIdx.y == 0);
    const float* __restrict__ W = is_lin ? w_lin : w_res;
    const int node0 = blockIdx.x * 64;

    // stage att vectors (only read by is_lin epilogue)
    if (tid < 128) {
        reinterpret_cast<float*>(smem + SM_ATT)[tid] = att_l[tid];
        reinterpret_cast<float*>(smem + SM_ATT)[128 + tid] = att_r[tid];
    }

    // ---- load A (64 nodes x 128 k), split hi/lo bf16 ----
    for (int i = tid; i < 64 * 32; i += 256) {
        int r = i >> 5, k4 = i & 31;
        int gnode = node0 + r;
        float4 v = make_float4(0.f, 0.f, 0.f, 0.f);
        if (gnode < N_NODES)
            v = reinterpret_cast<const float4*>(feature + (size_t)gnode * 128)[k4];
        const float vv[4] = {v.x, v.y, v.z, v.w};
        __nv_bfloat16 hi[4], lo[4];
        #pragma unroll
        for (int j = 0; j < 4; j++) {
            hi[j] = __float2bfloat16(vv[j]);
            lo[j] = __float2bfloat16(vv[j] - __bfloat162float(hi[j]));
        }
        size_t o = (size_t)(r * APAD + k4 * 4) * 2;
        *reinterpret_cast<uint2*>(smem + SM_AH + o) = *reinterpret_cast<uint2*>(hi);
        *reinterpret_cast<uint2*>(smem + SM_AL + o) = *reinterpret_cast<uint2*>(lo);
    }
    // ---- load B = W (128 k x 128 cols), split hi/lo ----
    for (int i = tid; i < 128 * 32; i += 256) {
        int k = i >> 5, c4 = i & 31;
        float4 v = reinterpret_cast<const float4*>(W + (size_t)k * 128)[c4];
        const float vv[4] = {v.x, v.y, v.z, v.w};
        __nv_bfloat16 hi[4], lo[4];
        #pragma unroll
        for (int j = 0; j < 4; j++) {
            hi[j] = __float2bfloat16(vv[j]);
            lo[j] = __float2bfloat16(vv[j] - __bfloat162float(hi[j]));
        }
        size_t o = (size_t)(k * APAD + c4 * 4) * 2;
        *reinterpret_cast<uint2*>(smem + SM_BH + o) = *reinterpret_cast<uint2*>(hi);
        *reinterpret_cast<uint2*>(smem + SM_BL + o) = *reinterpret_cast<uint2*>(lo);
    }
    __syncthreads();

    float c[2][4][4];
    #pragma unroll
    for (int mf = 0; mf < 2; mf++)
        #pragma unroll
        for (int nf = 0; nf < 4; nf++)
            #pragma unroll
            for (int q = 0; q < 4; q++) c[mf][nf][q] = 0.f;

    const int mi = lane >> 3, l7 = lane & 7;
    #pragma unroll
    for (int ks = 0; ks < 8; ks++) {
        uint32_t ah[2][4], alo[2][4], bh[4][2], bl[4][2];
        #pragma unroll
        for (int mf = 0; mf < 2; mf++) {
            int arow = wm * 32 + mf * 16 + ((mi & 1) << 3) + l7;
            int acol = ks * 16 + ((mi >> 1) << 3);
            uint32_t off = (uint32_t)(arow * APAD + acol) * 2;
            ldsm4(ah[mf], sb + SM_AH + off);
            ldsm4(alo[mf], sb + SM_AL + off);
        }
        #pragma unroll
        for (int np = 0; np < 2; np++) {
            int brow = ks * 16 + ((mi & 1) << 3) + l7;
            int bcol = wn * 32 + np * 16 + ((mi >> 1) << 3);
            uint32_t off = (uint32_t)(brow * APAD + bcol) * 2;
            uint32_t t[4];
            ldsm4t(t, sb + SM_BH + off);
            bh[2 * np][0] = t[0]; bh[2 * np][1] = t[1];
            bh[2 * np + 1][0] = t[2]; bh[2 * np + 1][1] = t[3];
            ldsm4t(t, sb + SM_BL + off);
            bl[2 * np][0] = t[0]; bl[2 * np][1] = t[1];
            bl[2 * np + 1][0] = t[2]; bl[2 * np + 1][1] = t[3];
        }
        #pragma unroll
        for (int mf = 0; mf < 2; mf++)
            #pragma unroll
            for (int nf = 0; nf < 4; nf++) {
                mma16816(c[mf][nf], ah[mf], bh[nf]);
                mma16816(c[mf][nf], alo[mf], bh[nf]);
                mma16816(c[mf][nf], ah[mf], bl[nf]);
            }
    }

    // ---- epilogue ----
    // C frag layout: c[0],c[1] -> row (lane>>2), cols 2(lane&3)+{0,1}; c[2],c[3] -> row+8.
    const float* sAl = reinterpret_cast<const float*>(smem + SM_ATT);
    const float* sAr = reinterpret_cast<const float*>(smem + SM_ATT) + 128;
    #pragma unroll
    for (int mf = 0; mf < 2; mf++) {
        int row_lo = node0 + wm * 32 + mf * 16 + (lane >> 2);
        int row_hi = row_lo + 8;
        bool ok_lo = row_lo < N_NODES, ok_hi = row_hi < N_NODES;
        if (is_lin) {
            // fp16 mirror
            #pragma unroll
            for (int nf = 0; nf < 4; nf++) {
                int col = wn * 32 + nf * 8 + ((lane & 3) << 1);
                __half2 hlo = __floats2half2_rn(c[mf][nf][0], c[mf][nf][1]);
                __half2 hhi = __floats2half2_rn(c[mf][nf][2], c[mf][nf][3]);
                if (ok_lo) *reinterpret_cast<__half2*>(g_xh + (size_t)row_lo * 128 + col) = hlo;
                if (ok_hi) *reinterpret_cast<__half2*>(g_xh + (size_t)row_hi * 128 + col) = hhi;
            }
            // logits: head hh covers frags {2hh, 2hh+1} (16 cols within this warp)
            #pragma unroll
            for (int hh = 0; hh < 2; hh++) {
                float sll = 0.f, srl = 0.f, slh = 0.f, srh = 0.f;
                #pragma unroll
                for (int f = 0; f < 2; f++) {
                    int nf = 2 * hh + f;
                    int col = wn * 32 + nf * 8 + ((lane & 3) << 1);
                    float w0l = sAl[col], w1l = sAl[col + 1];
                    float w0r = sAr[col], w1r = sAr[col + 1];
                    sll += c[mf][nf][0] * w0l + c[mf][nf][1] * w1l;
                    srl += c[mf][nf][0] * w0r + c[mf][nf][1] * w1r;
                    slh += c[mf][nf][2] * w0l + c[mf][nf][3] * w1l;
                    srh += c[mf][nf][2] * w0r + c[mf][nf][3] * w1r;
                }
                sll += __shfl_xor_sync(0xFFFFFFFFu, sll, 1);
                sll += __shfl_xor_sync(0xFFFFFFFFu, sll, 2);
                srl += __shfl_xor_sync(0xFFFFFFFFu, srl, 1);
                srl += __shfl_xor_sync(0xFFFFFFFFu, srl, 2);
                slh += __shfl_xor_sync(0xFFFFFFFFu, slh, 1);
                slh += __shfl_xor_sync(0xFFFFFFFFu, slh, 2);
                srh += __shfl_xor_sync(0xFFFFFFFFu, srh, 1);
                srh += __shfl_xor_sync(0xFFFFFFFFu, srh, 2);
                if ((lane & 3) == 0) {
                    int head = wn * 2 + hh;
                    if (ok_lo) { g_al[row_lo * 8 + head] = sll; g_ar[row_lo * 8 + head] = srl; }
                    if (ok_hi) { g_al[row_hi * 8 + head] = slh; g_ar[row_hi * 8 + head] = srh; }
                }
            }
        } else {
            #pragma unroll
            for (int nf = 0; nf < 4; nf++) {
                int col = wn * 32 + nf * 8 + ((lane & 3) << 1);
                if (ok_lo)
                    *reinterpret_cast<float2*>(d_out + (size_t)row_lo * 128 + col) =
                        make_float2(c[mf][nf][0], c[mf][nf][1]);
                if (ok_hi)
                    *reinterpret_cast<float2*>(d_out + (size_t)row_hi * 128 + col) =
                        make_float2(c[mf][nf][2], c[mf][nf][3]);
            }
        }
    }
}

// ---------------- histogram of dst (int4 vectorized) ----------------
__global__ void k_hist(const int* __restrict__ edst, int E) {
    int i = blockIdx.x * blockDim.x + threadIdx.x;
    if (i * 4 >= E) return;
    int4 d = reinterpret_cast<const int4*>(edst)[i];
    atomicAdd(&g_count[d.x], 1);
    atomicAdd(&g_count[d.y], 1);
    atomicAdd(&g_count[d.z], 1);
    atomicAdd(&g_count[d.w], 1);
}

// ---------------- single-block exclusive scan over 50K counts ----------------
__global__ __launch_bounds__(1024) void k_scan() {
    __shared__ int warp_sums[32];
    __shared__ int s_carry;
    int tid = threadIdx.x, lane = tid & 31, wid = tid >> 5;
    if (tid == 0) s_carry = 0;
    __syncthreads();
    for (int base = 0; base < N_NODES; base += 1024) {
        int i = base + tid;
        int v = (i < N_NODES) ? g_count[i] : 0;
        int incl = v;
        #pragma unroll
        for (int o = 1; o < 32; o <<= 1) {
            int t = __shfl_up_sync(0xFFFFFFFFu, incl, o);
            if (lane >= o) incl += t;
        }
        if (lane == 31) warp_sums[wid] = incl;
        __syncthreads();
        if (wid == 0) {
            int ws = warp_sums[lane];
            int wincl = ws;
            #pragma unroll
            for (int o = 1; o < 32; o <<= 1) {
                int t = __shfl_up_sync(0xFFFFFFFFu, wincl, o);
                if (lane >= o) wincl += t;
            }
            warp_sums[lane] = wincl - ws;   // exclusive warp prefix
        }
        __syncthreads();
        int excl = incl - v + warp_sums[wid] + s_carry;
        if (i < N_NODES) { g_rowptr[i] = excl; g_cursor[i] = excl; }
        __syncthreads();
        if (tid == 1023) s_carry += warp_sums[31] + incl;  // chunk total
        __syncthreads();
    }
    if (threadIdx.x == 0) g_rowptr[N_NODES] = s_carry;
}

// ---------------- scatter edges into dst-sorted order (x4) ----------------
__global__ void k_scatter(const int* __restrict__ esrc, const int* __restrict__ edst,
                          const float* __restrict__ ew, int E) {
    int i = blockIdx.x * blockDim.x + threadIdx.x;
    if (i * 4 >= E) return;
    int4 s = reinterpret_cast<const int4*>(esrc)[i];
    int4 d = reinterpret_cast<const int4*>(edst)[i];
    float4 w = reinterpret_cast<const float4*>(ew)[i];
    int p;
    p = atomicAdd(&g_cursor[d.x], 1); g_edge[p] = make_int2(s.x, __float_as_int(w.x));
    p = atomicAdd(&g_cursor[d.y], 1); g_edge[p] = make_int2(s.y, __float_as_int(w.y));
    p = atomicAdd(&g_cursor[d.z], 1); g_edge[p] = make_int2(s.z, __float_as_int(w.z));
    p = atomicAdd(&g_cursor[d.w], 1); g_edge[p] = make_int2(s.w, __float_as_int(w.w));
}

// ---------------- aggregate: one warp per dst node, fused finalize ----------------
__global__ __launch_bounds__(256) void k_agg(float* __restrict__ d_out) {
    int node = (blockIdx.x * blockDim.x + threadIdx.x) >> 5;
    if (node >= N_NODES) return;
    int lane = threadIdx.x & 31;
    int h = lane >> 2;
    int beg = __ldg(&g_rowptr[node]);
    int end = __ldg(&g_rowptr[node + 1]);
    float arv = g_ar[node * 8 + h];

    float a0 = 0.f, a1 = 0.f, a2 = 0.f, a3 = 0.f, dsum = 0.f;
    int e = beg;
    for (; e + 4 <= end; e += 4) {
        int2 ed[4];
        #pragma unroll
        for (int j = 0; j < 4; j++) ed[j] = __ldg(&g_edge[e + j]);
        float al[4];
        uint2 xh[4];
        #pragma unroll
        for (int j = 0; j < 4; j++) {
            al[j] = __ldg(&g_al[ed[j].x * 8 + h]);
            xh[j] = __ldg(reinterpret_cast<const uint2*>(g_xh + (size_t)ed[j].x * 128) + lane);
        }
        #pragma unroll
        for (int j = 0; j < 4; j++) {
            float aa = __int_as_float(ed[j].y) * (al[j] + arv);
            aa = (aa > 0.f) ? aa : 0.2f * aa;
            float ee = __expf(aa);
            dsum += ee;
            float2 lo = __half22float2(*reinterpret_cast<const __half2*>(&xh[j].x));
            float2 hi = __half22float2(*reinterpret_cast<const __half2*>(&xh[j].y));
            a0 += ee * lo.x;
            a1 += ee * lo.y;
            a2 += ee * hi.x;
            a3 += ee * hi.y;
        }
    }
    for (; e < end; e++) {
        int2 e0 = __ldg(&g_edge[e]);
        float al0 = __ldg(&g_al[e0.x * 8 + h]);
        uint2 x0 = __ldg(reinterpret_cast<const uint2*>(g_xh + (size_t)e0.x * 128) + lane);
        float aa0 = __int_as_float(e0.y) * (al0 + arv);
        aa0 = (aa0 > 0.f) ? aa0 : 0.2f * aa0;
        float ee0 = __expf(aa0);
        dsum += ee0;
        float2 lo = __half22float2(*reinterpret_cast<const __half2*>(&x0.x));
        float2 hi = __half22float2(*reinterpret_cast<const __half2*>(&x0.y));
        a0 += ee0 * lo.x; a1 += ee0 * lo.y; a2 += ee0 * hi.x; a3 += ee0 * hi.y;
    }

    float inv = (dsum > 0.f) ? 1.f / dsum : 0.f;
    float4 o = reinterpret_cast<float4*>(d_out)[node * 32 + lane];
    float v;
    v = a0 * inv; o.x += (v > 0.f) ? v : (__expf(v) - 1.f);
    v = a1 * inv; o.y += (v > 0.f) ? v : (__expf(v) - 1.f);
    v = a2 * inv; o.z += (v > 0.f) ? v : (__expf(v) - 1.f);
    v = a3 * inv; o.w += (v > 0.f) ? v : (__expf(v) - 1.f);
    reinterpret_cast<float4*>(d_out)[node * 32 + lane] = o;
}

extern "C" void kernel_launch(void* const* d_in, const int* in_sizes, int n_in,
                              void* d_out, int out_size) {
    const float* feature = (const float*)d_in[0];
    const int*   esrc    = (const int*)d_in[1];
    const int*   edst    = (const int*)d_in[2];
    const float* ew      = (const float*)d_in[3];
    const float* w_lin   = (const float*)d_in[4];
    const float* att_l   = (const float*)d_in[5];
    const float* att_r   = (const float*)d_in[6];
    const float* w_res   = (const float*)d_in[7];
    float* out = (float*)d_out;
    const int E = in_sizes[1];

    static cudaStream_t s_side = nullptr;
    static cudaEvent_t ev_fork = nullptr, ev_join = nullptr;
    if (s_side == nullptr) {
        cudaStreamCreateWithFlags(&s_side, cudaStreamNonBlocking);
        cudaEventCreateWithFlags(&ev_fork, cudaEventDisableTiming);
        cudaEventCreateWithFlags(&ev_join, cudaEventDisableTiming);
        cudaFuncSetAttribute(k_gemm, cudaFuncAttributeMaxDynamicSharedMemorySize, SM_TOT);
    }

    const int e4 = E / 4;

    // Fork: CSR build on side stream; k_gemm stays the 4th issued (profiled).
    cudaEventRecord(ev_fork, 0);
    cudaStreamWaitEvent(s_side, ev_fork, 0);
    k_zero<<<(N_NODES + 255) / 256, 256, 0, s_side>>>();
    k_hist<<<(e4 + 255) / 256, 256, 0, s_side>>>(edst, E);
    k_scan<<<1, 1024, 0, s_side>>>();

    dim3 gg((N_NODES + 63) / 64, 2);
    k_gemm<<<gg, 256, SM_TOT>>>(feature, w_lin, w_res, att_l, att_r, out);

    k_scatter<<<(e4 + 255) / 256, 256, 0, s_side>>>(esrc, edst, ew, E);
    cudaEventRecord(ev_join, s_side);

    cudaStreamWaitEvent(0, ev_join, 0);
    k_agg<<<(N_NODES * 32 + 255) / 256, 256>>>(out);
}